// round 2
// baseline (speedup 1.0000x reference)
#include <cuda_runtime.h>

// CFConv: y[i] = sum_{e: idx_i[e]==i} x[idx_j[e]] * Wij[e]
// x:[50000,64] f32, Wij:[E=1.25M,64] f32, idx_i sorted.
//
// R2: tile-batched loads (T=8) for gather MLP; packed int2 index scratch;
//     sorted-segment register accumulation with boundary atomics.

#define CHUNK 128
#define TILE  8
#define FEAT  64
#define MAX_E 1250000

__device__ int2 g_idx[MAX_E];

// Pack idx_i/idx_j (int64 or int32, runtime-probed) into int2 {i, j}.
__global__ __launch_bounds__(256) void pack_idx_kernel(
    const void* __restrict__ ii_p, const void* __restrict__ jj_p, int E)
{
    int e = blockIdx.x * blockDim.x + threadIdx.x;
    if (e >= E) return;
    // dtype probe: for LE int64 data the int32 word at odd position (E/2)|1 is a
    // high word == 0 (indices < 2^31); for int32 the sorted median ~N/2 != 0.
    int probe = reinterpret_cast<const int*>(ii_p)[(E / 2) | 1];
    int a, b;
    if (probe == 0) {
        a = (int)reinterpret_cast<const long long*>(ii_p)[e];
        b = (int)reinterpret_cast<const long long*>(jj_p)[e];
    } else {
        a = reinterpret_cast<const int*>(ii_p)[e];
        b = reinterpret_cast<const int*>(jj_p)[e];
    }
    g_idx[e] = make_int2(a, b);
}

__device__ __forceinline__ void flush_seg(float* __restrict__ y, int seg,
                                          int lane, float2 acc, bool& first)
{
    float* dst = y + (long long)seg * FEAT + lane * 2;
    if (first) {               // may extend into previous chunk -> atomic
        atomicAdd(dst,     acc.x);
        atomicAdd(dst + 1, acc.y);
        first = false;
    } else {                   // interior segment: exclusively owned -> store
        *reinterpret_cast<float2*>(dst) = acc;
    }
}

__global__ __launch_bounds__(256) void cfconv_kernel(
    const float2* __restrict__ x2, const float2* __restrict__ W2,
    float* __restrict__ y, int E)
{
    int gwarp = (blockIdx.x * blockDim.x + threadIdx.x) >> 5;
    int lane  = threadIdx.x & 31;

    long long e = (long long)gwarp * CHUNK;
    if (e >= E) return;
    long long eEnd = e + CHUNK;
    if (eEnd > E) eEnd = E;

    int   prev  = g_idx[e].x;
    bool  first = true;
    float2 acc  = make_float2(0.f, 0.f);

    // ---- tiled main loop: batch all loads, then accumulate ----
    for (; e + TILE <= eEnd; e += TILE) {
        int2   id[TILE];
        float2 w [TILE];
        float2 xv[TILE];
        #pragma unroll
        for (int t = 0; t < TILE; ++t)
            id[t] = g_idx[e + t];
        #pragma unroll
        for (int t = 0; t < TILE; ++t)
            w[t] = W2[(e + t) * (FEAT / 2) + lane];
        #pragma unroll
        for (int t = 0; t < TILE; ++t)
            xv[t] = x2[(long long)id[t].y * (FEAT / 2) + lane];
        #pragma unroll
        for (int t = 0; t < TILE; ++t) {
            if (id[t].x != prev) {
                flush_seg(y, prev, lane, acc, first);
                acc  = make_float2(0.f, 0.f);
                prev = id[t].x;
            }
            acc.x = fmaf(xv[t].x, w[t].x, acc.x);
            acc.y = fmaf(xv[t].y, w[t].y, acc.y);
        }
    }
    // ---- scalar tail ----
    for (; e < eEnd; ++e) {
        int2   id = g_idx[e];
        float2 w  = W2[e * (FEAT / 2) + lane];
        float2 xv = x2[(long long)id.y * (FEAT / 2) + lane];
        if (id.x != prev) {
            flush_seg(y, prev, lane, acc, first);
            acc  = make_float2(0.f, 0.f);
            prev = id.x;
        }
        acc.x = fmaf(xv.x, w.x, acc.x);
        acc.y = fmaf(xv.y, w.y, acc.y);
    }
    // last segment may extend into next chunk -> atomic
    float* dst = y + (long long)prev * FEAT + lane * 2;
    atomicAdd(dst,     acc.x);
    atomicAdd(dst + 1, acc.y);
}

extern "C" void kernel_launch(void* const* d_in, const int* in_sizes, int n_in,
                              void* d_out, int out_size)
{
    const float* x   = (const float*)d_in[0];   // [N, 64]
    const float* Wij = (const float*)d_in[1];   // [E, 64]
    const void*  ii  = d_in[2];                 // [E] int64 or int32
    const void*  jj  = d_in[3];                 // [E] int64 or int32
    float*       y   = (float*)d_out;           // [N, 64]

    int E = in_sizes[1] / FEAT;                 // dtype-independent edge count

    // zero output (memset node — graph-capturable)
    cudaMemsetAsync(d_out, 0, (size_t)out_size * sizeof(float), 0);

    // pack indices into int2 scratch
    pack_idx_kernel<<<(E + 255) / 256, 256>>>(ii, jj, E);

    // main segmented gather-multiply-scatter
    int nwarps  = (E + CHUNK - 1) / CHUNK;
    int nblocks = (nwarps + 7) / 8;
    cfconv_kernel<<<nblocks, 256>>>((const float2*)x, (const float2*)Wij, y, E);
}

// round 3
// speedup vs baseline: 2.3017x; 2.3017x over previous
#include <cuda_runtime.h>

// CFConv: y[i] = sum_{e: idx_i[e]==i} x[idx_j[e]] * Wij[e]
// x:[50000,64] f32, Wij:[E=1.25M,64] f32, idx_i sorted.
//
// R3: half-warp virtual warps (16 lanes x float4 = 64 features), each half
// owns a contiguous HALF-edge range -> ~8 instr/edge (vs ~30), sorted-segment
// register accumulation, plain stores for interior segments, vector RED for
// boundary segments, __ldcs streaming on Wij to keep x L2-resident.

#define FEAT   64
#define F4     (FEAT / 4)      // 16 float4 per row
#define HALF   128             // edges per half-warp
#define CHUNK  (2 * HALF)      // edges per warp
#define MAX_E  1250000

__device__ int2 g_idx[MAX_E];

// Pack idx_i/idx_j (int64 or int32, runtime-probed) into int2 {i, j}.
__global__ __launch_bounds__(256) void pack_idx_kernel(
    const void* __restrict__ ii_p, const void* __restrict__ jj_p, int E)
{
    int e = blockIdx.x * blockDim.x + threadIdx.x;
    if (e >= E) return;
    // LE int64 data: int32 word at odd position (E/2)|1 is a high word == 0.
    // int32 data: sorted idx_i median ~N/2 != 0.
    int probe = reinterpret_cast<const int*>(ii_p)[(E / 2) | 1];
    int a, b;
    if (probe == 0) {
        a = (int)reinterpret_cast<const long long*>(ii_p)[e];
        b = (int)reinterpret_cast<const long long*>(jj_p)[e];
    } else {
        a = reinterpret_cast<const int*>(ii_p)[e];
        b = reinterpret_cast<const int*>(jj_p)[e];
    }
    g_idx[e] = make_int2(a, b);
}

__device__ __forceinline__ void red_add_f4(float* p, float4 v) {
    asm volatile("red.global.add.v4.f32 [%0], {%1,%2,%3,%4};"
                 :: "l"(p), "f"(v.x), "f"(v.y), "f"(v.z), "f"(v.w)
                 : "memory");
}

__global__ __launch_bounds__(256, 5) void cfconv_kernel(
    const float4* __restrict__ X4, const float4* __restrict__ W4,
    float* __restrict__ y, int E)
{
    int gwarp = (blockIdx.x * blockDim.x + threadIdx.x) >> 5;
    int lane  = threadIdx.x & 31;
    int half  = lane >> 4;         // which half-warp
    int fl    = lane & 15;         // float4 slot within the feature row

    long long base = (long long)gwarp * CHUNK;
    if (base >= E) return;

    long long s  = base + (long long)half * HALF;
    long long se = s + HALF;
    if (se > E) se = E;
    int cnt = (s < E) ? (int)(se - s) : 0;   // edges this half processes
    if (cnt <= 0) return;                    // inactive half (tail chunk)

    const int2*   ip = g_idx + s;
    const float4* wp = W4 + (size_t)s * F4 + fl;

    // primer: edge 0
    int2   idc = ip[0];
    float4 wc  = __ldcs(wp);
    float4 xc  = X4[(size_t)idc.y * F4 + fl];

    int    prev  = idc.x;
    bool   first = true;           // first segment may start before s -> atomic
    float4 acc   = make_float4(0.f, 0.f, 0.f, 0.f);

    for (int k = 1; k < cnt; ++k) {
        // issue next-iteration loads before consuming current (depth-1 pipeline)
        int2   idn = ip[k];
        float4 wn  = __ldcs(wp + (size_t)k * F4);
        float4 xn  = X4[(size_t)idn.y * F4 + fl];

        // process current edge
        if (idc.x != prev) {
            float* dst = y + (size_t)prev * FEAT + fl * 4;
            if (first) { red_add_f4(dst, acc); first = false; }
            else       { *reinterpret_cast<float4*>(dst) = acc; }  // exclusive interior segment
            acc  = make_float4(0.f, 0.f, 0.f, 0.f);
            prev = idc.x;
        }
        acc.x = fmaf(xc.x, wc.x, acc.x);
        acc.y = fmaf(xc.y, wc.y, acc.y);
        acc.z = fmaf(xc.z, wc.z, acc.z);
        acc.w = fmaf(xc.w, wc.w, acc.w);

        idc = idn; wc = wn; xc = xn;
    }

    // last edge
    if (idc.x != prev) {
        float* dst = y + (size_t)prev * FEAT + fl * 4;
        if (first) { red_add_f4(dst, acc); first = false; }
        else       { *reinterpret_cast<float4*>(dst) = acc; }
        acc  = make_float4(0.f, 0.f, 0.f, 0.f);
        prev = idc.x;
    }
    acc.x = fmaf(xc.x, wc.x, acc.x);
    acc.y = fmaf(xc.y, wc.y, acc.y);
    acc.z = fmaf(xc.z, wc.z, acc.z);
    acc.w = fmaf(xc.w, wc.w, acc.w);

    // final segment may extend into the next sub-chunk -> atomic
    red_add_f4(y + (size_t)prev * FEAT + fl * 4, acc);
}

extern "C" void kernel_launch(void* const* d_in, const int* in_sizes, int n_in,
                              void* d_out, int out_size)
{
    const float* x   = (const float*)d_in[0];   // [N, 64]
    const float* Wij = (const float*)d_in[1];   // [E, 64]
    const void*  ii  = d_in[2];                 // [E] int64 or int32
    const void*  jj  = d_in[3];                 // [E] int64 or int32
    float*       y   = (float*)d_out;           // [N, 64]

    int E = in_sizes[1] / FEAT;

    // zero output (memset node — graph-capturable)
    cudaMemsetAsync(d_out, 0, (size_t)out_size * sizeof(float), 0);

    // pack indices into int2 scratch
    pack_idx_kernel<<<(E + 255) / 256, 256>>>(ii, jj, E);

    // main segmented gather-multiply-scatter
    int nwarps  = (E + CHUNK - 1) / CHUNK;
    int nblocks = (nwarps + 7) / 8;             // 8 warps / 256-thread block
    cfconv_kernel<<<nblocks, 256>>>((const float4*)x, (const float4*)Wij, y, E);
}